// round 14
// baseline (speedup 1.0000x reference)
#include <cuda_runtime.h>
#include <cuda_fp16.h>
#include <cstdint>

#define N_NODES 100000
#define FEAT 64
#define HID 128
#define N_EDGES 1200000
#define SCAN_B 1024
#define N_SCANB 98
#define NT64 ((N_NODES + 63) / 64)   // 1563 tiles of 64 nodes
#define PA 132                       // padded row stride (floats)
#define PGRID 296                    // persistent grid: 2 CTAs/SM x 148 SMs

// Scratch (device globals — no allocation allowed)
__device__ float  g_agg[N_NODES * FEAT];   // tf32-pre-rounded mean aggregate
__device__ float  g_h[N_NODES * HID];      // hidden activations (tf32-rounded)
__device__ __half g_hlh[N_NODES * FEAT];   // h @ W2l.T in fp16 (pre-aggregation)
__device__ __half g_xh[N_NODES * FEAT];    // x in fp16 (for gather1)
__device__ float  g_invdeg[N_NODES];
__device__ int    g_cnt[N_NODES];
__device__ int    g_rowptr[N_NODES];
__device__ int    g_pos[N_EDGES];          // within-node slot of each edge
__device__ int    g_csr[N_EDGES];
__device__ int    g_bsum[N_SCANB];

// ---------------------------------------------------------------------------
__device__ __forceinline__ float tf32r(float f) {
    uint32_t r;
    asm("cvt.rna.tf32.f32 %0, %1;" : "=r"(r) : "f"(f));
    return __uint_as_float(r);
}
__device__ __forceinline__ float4 tf32r4(float4 v) {
    return make_float4(tf32r(v.x), tf32r(v.y), tf32r(v.z), tf32r(v.w));
}
__device__ __forceinline__ void mma_tf32(float* d, const uint32_t* a, const uint32_t* b) {
    asm volatile(
        "mma.sync.aligned.m16n8k8.row.col.f32.tf32.tf32.f32 "
        "{%0,%1,%2,%3}, {%4,%5,%6,%7}, {%8,%9}, {%0,%1,%2,%3};"
        : "+f"(d[0]), "+f"(d[1]), "+f"(d[2]), "+f"(d[3])
        : "r"(a[0]), "r"(a[1]), "r"(a[2]), "r"(a[3]), "r"(b[0]), "r"(b[1]));
}
__device__ __forceinline__ uint32_t smem_u32(const void* p) {
    uint32_t a;
    asm("{ .reg .u64 t; cvta.to.shared.u64 t, %1; cvt.u32.u64 %0, t; }" : "=r"(a) : "l"(p));
    return a;
}
__device__ __forceinline__ void cpasync16(uint32_t dst, const void* src, int pred16) {
    asm volatile("cp.async.cg.shared.global [%0], [%1], 16, %2;"
                 :: "r"(dst), "l"(src), "r"(pred16) : "memory");
}
#define CP_COMMIT() asm volatile("cp.async.commit_group;" ::: "memory")
#define CP_WAIT0()  asm volatile("cp.async.wait_group 0;" ::: "memory")

// --------------------------- x -> fp16 pre-pass -----------------------------
__global__ void xcvt_kernel(const float* __restrict__ x) {
    int i = blockIdx.x * blockDim.x + threadIdx.x;
    if (i >= N_NODES * FEAT / 4) return;
    float4 v = ((const float4*)x)[i];
    __half2* dst = (__half2*)g_xh + i * 2;
    dst[0] = __floats2half2_rn(v.x, v.y);
    dst[1] = __floats2half2_rn(v.z, v.w);
}

// --------------------------- CSR build ------------------------------------
__global__ void hist_kernel(const int* __restrict__ ei) {
    int e4 = blockIdx.x * blockDim.x + threadIdx.x;
    if (e4 >= N_EDGES / 4) return;
    int4 d = ((const int4*)(ei + N_EDGES))[e4];
    int p0 = atomicAdd(&g_cnt[d.x], 1);
    int p1 = atomicAdd(&g_cnt[d.y], 1);
    int p2 = atomicAdd(&g_cnt[d.z], 1);
    int p3 = atomicAdd(&g_cnt[d.w], 1);
    ((int4*)g_pos)[e4] = make_int4(p0, p1, p2, p3);
}

__global__ void scan1_kernel() {
    __shared__ int ws[8];
    int b = blockIdx.x, t = threadIdx.x;
    int base = b * SCAN_B + t * 4;
    int c0 = (base + 0 < N_NODES) ? g_cnt[base + 0] : 0;
    int c1 = (base + 1 < N_NODES) ? g_cnt[base + 1] : 0;
    int c2 = (base + 2 < N_NODES) ? g_cnt[base + 2] : 0;
    int c3 = (base + 3 < N_NODES) ? g_cnt[base + 3] : 0;
    int s = c0 + c1 + c2 + c3;
    int lane = t & 31, w = t >> 5;
    int v = s;
    #pragma unroll
    for (int d = 1; d < 32; d <<= 1) {
        int u = __shfl_up_sync(~0u, v, d);
        if (lane >= d) v += u;
    }
    if (lane == 31) ws[w] = v;
    __syncthreads();
    if (t < 8) {
        int u = ws[t];
        #pragma unroll
        for (int d = 1; d < 8; d <<= 1) {
            int uu = __shfl_up_sync(0xffu, u, d);
            if (t >= d) u += uu;
        }
        ws[t] = u;
    }
    __syncthreads();
    int prefix = v - s + ((w > 0) ? ws[w - 1] : 0);
    int r0 = prefix, r1 = r0 + c0, r2 = r1 + c1, r3 = r2 + c2;
    if (base + 0 < N_NODES) g_rowptr[base + 0] = r0;
    if (base + 1 < N_NODES) g_rowptr[base + 1] = r1;
    if (base + 2 < N_NODES) g_rowptr[base + 2] = r2;
    if (base + 3 < N_NODES) g_rowptr[base + 3] = r3;
    if (t == 255) g_bsum[b] = ws[7];
}

__global__ void scan3_kernel() {
    __shared__ int red[256];
    __shared__ int off;
    int t = threadIdx.x;
    int sb = (blockIdx.x * 256) / SCAN_B;
    int partial = 0;
    for (int i = t; i < sb; i += 256) partial += g_bsum[i];
    red[t] = partial;
    __syncthreads();
    #pragma unroll
    for (int d = 128; d > 0; d >>= 1) {
        if (t < d) red[t] += red[t + d];
        __syncthreads();
    }
    if (t == 0) off = red[0];
    __syncthreads();
    int i = blockIdx.x * 256 + t;
    if (i >= N_NODES) return;
    g_rowptr[i] += off;
    g_invdeg[i] = 1.0f / fmaxf((float)g_cnt[i], 1.0f);
}

// fill: no atomics — slot comes from hist's g_pos
__global__ void fill_kernel(const int* __restrict__ ei) {
    int e4 = blockIdx.x * blockDim.x + threadIdx.x;
    if (e4 >= N_EDGES / 4) return;
    int4 s = ((const int4*)ei)[e4];
    int4 d = ((const int4*)(ei + N_EDGES))[e4];
    int4 p = ((const int4*)g_pos)[e4];
    g_csr[g_rowptr[d.x] + p.x] = s.x;
    g_csr[g_rowptr[d.y] + p.y] = s.y;
    g_csr[g_rowptr[d.z] + p.z] = s.z;
    g_csr[g_rowptr[d.w] + p.w] = s.w;
}

// ------------- Gather 1 (fp16 x -> fp32 agg, mean, tf32-rounded) ------------
__global__ void gather_kernel(float* __restrict__ aggm) {
    int gw = (blockIdx.x * blockDim.x + threadIdx.x) >> 5;
    if (gw >= N_NODES) return;
    int lane = threadIdx.x & 31;
    int start = g_rowptr[gw];
    int deg = g_cnt[gw];
    const __half2* v2 = (const __half2*)g_xh;
    float2 a0 = make_float2(0.f, 0.f), a1 = make_float2(0.f, 0.f);
    float2 a2 = make_float2(0.f, 0.f), a3 = make_float2(0.f, 0.f);
    int i = 0;
    for (; i + 4 <= deg; i += 4) {
        int s0 = g_csr[start + i];
        int s1 = g_csr[start + i + 1];
        int s2 = g_csr[start + i + 2];
        int s3 = g_csr[start + i + 3];
        float2 u0 = __half22float2(v2[(size_t)s0 * 32 + lane]);
        float2 u1 = __half22float2(v2[(size_t)s1 * 32 + lane]);
        float2 u2 = __half22float2(v2[(size_t)s2 * 32 + lane]);
        float2 u3 = __half22float2(v2[(size_t)s3 * 32 + lane]);
        a0.x += u0.x; a0.y += u0.y;
        a1.x += u1.x; a1.y += u1.y;
        a2.x += u2.x; a2.y += u2.y;
        a3.x += u3.x; a3.y += u3.y;
    }
    for (; i < deg; i++) {
        float2 u0 = __half22float2(v2[(size_t)g_csr[start + i] * 32 + lane]);
        a0.x += u0.x; a0.y += u0.y;
    }
    float inv = g_invdeg[gw];
    ((float2*)aggm)[(size_t)gw * 32 + lane] =
        make_float2(tf32r(((a0.x + a1.x) + (a2.x + a3.x)) * inv),
                    tf32r(((a0.y + a1.y) + (a2.y + a3.y)) * inv));
}

// ------------- Gather 2 (fp16 hl) fused with final epilogue -----------------
__global__ void gather2_final_kernel(const float* __restrict__ b2l,
                                     float* __restrict__ out) {
    int gw = (blockIdx.x * blockDim.x + threadIdx.x) >> 5;
    if (gw >= N_NODES) return;
    int lane = threadIdx.x & 31;
    int start = g_rowptr[gw];
    int deg = g_cnt[gw];
    const __half2* v2 = (const __half2*)g_hlh;
    float2 a0 = make_float2(0.f, 0.f), a1 = make_float2(0.f, 0.f);
    float2 a2 = make_float2(0.f, 0.f), a3 = make_float2(0.f, 0.f);
    int i = 0;
    for (; i + 4 <= deg; i += 4) {
        int s0 = g_csr[start + i];
        int s1 = g_csr[start + i + 1];
        int s2 = g_csr[start + i + 2];
        int s3 = g_csr[start + i + 3];
        float2 u0 = __half22float2(v2[(size_t)s0 * 32 + lane]);
        float2 u1 = __half22float2(v2[(size_t)s1 * 32 + lane]);
        float2 u2 = __half22float2(v2[(size_t)s2 * 32 + lane]);
        float2 u3 = __half22float2(v2[(size_t)s3 * 32 + lane]);
        a0.x += u0.x; a0.y += u0.y;
        a1.x += u1.x; a1.y += u1.y;
        a2.x += u2.x; a2.y += u2.y;
        a3.x += u3.x; a3.y += u3.y;
    }
    for (; i < deg; i++) {
        float2 u0 = __half22float2(v2[(size_t)g_csr[start + i] * 32 + lane]);
        a0.x += u0.x; a0.y += u0.y;
    }
    float inv = g_invdeg[gw];
    float2 b = ((const float2*)b2l)[lane];
    float2* op = (float2*)out + (size_t)gw * 32 + lane;
    float2 y = *op;
    y.x += ((a0.x + a1.x) + (a2.x + a3.x)) * inv + b.x;
    y.y += ((a0.y + a1.y) + (a2.y + a3.y)) * inv + b.y;
    *op = y;
}

// --------------------------- tf32 mma.sync GEMM core ------------------------
__device__ __forceinline__ void gemm_core64(const float* sA, const float* sB,
                                            float acc[2][4][4],
                                            int g, int c, int wm, int wn) {
    #pragma unroll
    for (int ks = 0; ks < 16; ks++) {
        int K = ks * 8;
        uint32_t af[2][4];
        #pragma unroll
        for (int mt = 0; mt < 2; mt++) {
            const float* base = sA + (wm * 32 + mt * 16 + g) * PA + K + c;
            af[mt][0] = __float_as_uint(base[0]);
            af[mt][1] = __float_as_uint(base[8 * PA]);
            af[mt][2] = __float_as_uint(base[4]);
            af[mt][3] = __float_as_uint(base[8 * PA + 4]);
        }
        uint32_t bf[4][2];
        #pragma unroll
        for (int nt = 0; nt < 4; nt++) {
            const float* base = sB + (wn * 32 + nt * 8 + g) * PA + K + c;
            bf[nt][0] = __float_as_uint(base[0]);
            bf[nt][1] = __float_as_uint(base[4]);
        }
        #pragma unroll
        for (int mt = 0; mt < 2; mt++)
            #pragma unroll
            for (int nt = 0; nt < 4; nt++)
                mma_tf32(acc[mt][nt], af[mt], bf[nt]);
    }
}

// ----------- Layer 1 GEMM (persistent, B resident, prefetched A) ------------
__global__ void __launch_bounds__(256, 2)
layer1_mma_kernel(const float* __restrict__ x,
                  const float* __restrict__ W1l,
                  const float* __restrict__ b1l,
                  const float* __restrict__ W1r) {
    extern __shared__ float sm[];
    float* sA = sm;                        // 64 * PA
    float* sB = sm + 64 * PA;              // 128 * PA
    float* sbias = sm + 64 * PA + 128 * PA;
    uint32_t sA_u = smem_u32(sA);

    int t = threadIdx.x;
    int wid = t >> 5, lane = t & 31;
    int g = lane >> 2, c = lane & 3, wm = wid & 1, wn = wid >> 1;

    for (int i = t; i < 4096; i += 256) {
        int ch = i >> 5, f4 = i & 31;
        float4 w = (f4 < 16) ? ((const float4*)W1l)[ch * 16 + f4]
                             : ((const float4*)W1r)[ch * 16 + (f4 - 16)];
        *(float4*)&sB[ch * PA + f4 * 4] = tf32r4(w);
    }
    if (t < 128) sbias[t] = b1l[t];

    auto issueA = [&](int tile) {
        int n0 = tile * 64;
        #pragma unroll
        for (int s = 0; s < 4; s++) {
            int i = t + s * 256;
            int j = i >> 4, f4 = i & 15;
            int n = n0 + j;
            cpasync16(sA_u + (j * PA + f4 * 4) * 4,
                      g_agg + ((size_t)n * FEAT + f4 * 4),
                      (n < N_NODES) ? 16 : 0);
        }
        CP_COMMIT();
        #pragma unroll
        for (int s = 0; s < 4; s++) {
            int i = t + s * 256;
            int j = i >> 4, f4 = i & 15;
            int n = n0 + j;
            float4 v = make_float4(0.f, 0.f, 0.f, 0.f);
            if (n < N_NODES) v = ((const float4*)x)[(size_t)n * 16 + f4];
            *(float4*)&sA[j * PA + 64 + f4 * 4] = tf32r4(v);
        }
    };

    int tile = blockIdx.x;
    if (tile < NT64) issueA(tile);
    __syncthreads();

    for (; tile < NT64; tile += PGRID) {
        CP_WAIT0();
        __syncthreads();

        float acc[2][4][4];
        #pragma unroll
        for (int mt = 0; mt < 2; mt++)
            #pragma unroll
            for (int nt = 0; nt < 4; nt++)
                #pragma unroll
                for (int k = 0; k < 4; k++) acc[mt][nt][k] = 0.0f;

        gemm_core64(sA, sB, acc, g, c, wm, wn);
        __syncthreads();

        int next = tile + PGRID;
        if (next < NT64) issueA(next);

        int n0 = tile * 64;
        #pragma unroll
        for (int mt = 0; mt < 2; mt++) {
            int r0 = n0 + wm * 32 + mt * 16 + g;
            #pragma unroll
            for (int nt = 0; nt < 4; nt++) {
                int col = wn * 32 + nt * 8 + c * 2;
                float bx = sbias[col], by = sbias[col + 1];
                if (r0 < N_NODES)
                    *(float2*)&g_h[(size_t)r0 * HID + col] =
                        make_float2(tf32r(fmaxf(acc[mt][nt][0] + bx, 0.f)),
                                    tf32r(fmaxf(acc[mt][nt][1] + by, 0.f)));
                if (r0 + 8 < N_NODES)
                    *(float2*)&g_h[(size_t)(r0 + 8) * HID + col] =
                        make_float2(tf32r(fmaxf(acc[mt][nt][2] + bx, 0.f)),
                                    tf32r(fmaxf(acc[mt][nt][3] + by, 0.f)));
            }
        }
    }
}

// ------------- Layer 2 GEMM (persistent, B resident, cp.async A) ------------
__global__ void __launch_bounds__(256, 2)
gemm2_mma_kernel(const float* __restrict__ W2l,
                 const float* __restrict__ W2r,
                 float* __restrict__ out) {
    extern __shared__ float sm[];
    float* sA = sm;
    float* sB = sm + 64 * PA;
    uint32_t sA_u = smem_u32(sA);

    int t = threadIdx.x;
    int wid = t >> 5, lane = t & 31;
    int g = lane >> 2, c = lane & 3, wm = wid & 1, wn = wid >> 1;

    for (int i = t; i < 4096; i += 256) {
        int ch = i >> 5, f4 = i & 31;
        float4 w = (ch < 64) ? ((const float4*)W2l)[ch * 32 + f4]
                             : ((const float4*)W2r)[(ch - 64) * 32 + f4];
        *(float4*)&sB[ch * PA + f4 * 4] = tf32r4(w);
    }

    auto issueA = [&](int tile) {
        int n0 = tile * 64;
        #pragma unroll
        for (int s = 0; s < 8; s++) {
            int i = t + s * 256;
            int j = i >> 5, f4 = i & 31;
            int n = n0 + j;
            cpasync16(sA_u + (j * PA + f4 * 4) * 4,
                      (const char*)g_h + ((size_t)n * HID + f4 * 4) * 4,
                      (n < N_NODES) ? 16 : 0);
        }
        CP_COMMIT();
    };

    int tile = blockIdx.x;
    if (tile < NT64) issueA(tile);
    __syncthreads();

    for (; tile < NT64; tile += PGRID) {
        CP_WAIT0();
        __syncthreads();

        float acc[2][4][4];
        #pragma unroll
        for (int mt = 0; mt < 2; mt++)
            #pragma unroll
            for (int nt = 0; nt < 4; nt++)
                #pragma unroll
                for (int k = 0; k < 4; k++) acc[mt][nt][k] = 0.0f;

        gemm_core64(sA, sB, acc, g, c, wm, wn);
        __syncthreads();

        int next = tile + PGRID;
        if (next < NT64) issueA(next);

        int n0 = tile * 64;
        #pragma unroll
        for (int mt = 0; mt < 2; mt++) {
            int r0 = n0 + wm * 32 + mt * 16 + g;
            #pragma unroll
            for (int nt = 0; nt < 4; nt++) {
                int col = wn * 32 + nt * 8 + c * 2;
                if (wn < 2) {   // hl in fp16
                    if (r0 < N_NODES)
                        *(__half2*)&g_hlh[(size_t)r0 * FEAT + col] =
                            __floats2half2_rn(acc[mt][nt][0], acc[mt][nt][1]);
                    if (r0 + 8 < N_NODES)
                        *(__half2*)&g_hlh[(size_t)(r0 + 8) * FEAT + col] =
                            __floats2half2_rn(acc[mt][nt][2], acc[mt][nt][3]);
                } else {        // lin_r part straight to out (fp32)
                    int colo = col - 64;
                    if (r0 < N_NODES)
                        *(float2*)&out[(size_t)r0 * FEAT + colo] =
                            make_float2(acc[mt][nt][0], acc[mt][nt][1]);
                    if (r0 + 8 < N_NODES)
                        *(float2*)&out[(size_t)(r0 + 8) * FEAT + colo] =
                            make_float2(acc[mt][nt][2], acc[mt][nt][3]);
                }
            }
        }
    }
}

// ---------------------------------------------------------------------------
extern "C" void kernel_launch(void* const* d_in, const int* in_sizes, int n_in,
                              void* d_out, int out_size) {
    const float* x   = (const float*)d_in[0];
    const int*   ei  = (const int*)d_in[1];
    const float* W1l = (const float*)d_in[2];
    const float* b1l = (const float*)d_in[3];
    const float* W1r = (const float*)d_in[4];
    const float* W2l = (const float*)d_in[5];
    const float* b2l = (const float*)d_in[6];
    const float* W2r = (const float*)d_in[7];
    float* out = (float*)d_out;

    float *agg;
    int *cnt;
    cudaGetSymbolAddress((void**)&agg, g_agg);
    cudaGetSymbolAddress((void**)&cnt, g_cnt);

    const int SMEM1 = (64 * PA + 128 * PA + 128) * 4;   // 101,888 B
    const int SMEM2 = (64 * PA + 128 * PA) * 4;         // 101,376 B
    cudaFuncSetAttribute(layer1_mma_kernel, cudaFuncAttributeMaxDynamicSharedMemorySize, SMEM1);
    cudaFuncSetAttribute(gemm2_mma_kernel,  cudaFuncAttributeMaxDynamicSharedMemorySize, SMEM2);

    // CSR build + fp16 x conversion
    cudaMemsetAsync(cnt, 0, N_NODES * sizeof(int));
    xcvt_kernel<<<(N_NODES * FEAT / 4 + 255) / 256, 256>>>(x);
    hist_kernel<<<(N_EDGES / 4 + 255) / 256, 256>>>(ei);
    scan1_kernel<<<N_SCANB, 256>>>();
    scan3_kernel<<<(N_NODES + 255) / 256, 256>>>();
    fill_kernel<<<(N_EDGES / 4 + 255) / 256, 256>>>(ei);

    // Layer 1
    gather_kernel<<<(N_NODES * 32 + 255) / 256, 256>>>(agg);
    layer1_mma_kernel<<<PGRID, 256, SMEM1>>>(x, W1l, b1l, W1r);

    // Layer 2
    gemm2_mma_kernel<<<PGRID, 256, SMEM2>>>(W2l, W2r, out);
    gather2_final_kernel<<<(N_NODES * 32 + 255) / 256, 256>>>(b2l, out);
}

// round 17
// speedup vs baseline: 1.1169x; 1.1169x over previous
#include <cuda_runtime.h>
#include <cstdint>

#define N_NODES 100000
#define FEAT 64
#define HID 128
#define N_EDGES 1200000
#define SCAN_B 1024
#define N_SCANB 98
#define NT64 ((N_NODES + 63) / 64)   // 1563 tiles of 64 nodes
#define PA 132                       // padded row stride (floats)
#define PGRID 296                    // persistent grid: 2 CTAs/SM x 148 SMs

// Scratch (device globals — no allocation allowed)
__device__ float g_agg[N_NODES * FEAT];    // tf32-pre-rounded mean aggregate
__device__ float g_h[N_NODES * HID];       // hidden activations (tf32-rounded)
__device__ float g_hl[N_NODES * FEAT];
__device__ float g_invdeg[N_NODES];
__device__ int   g_cnt[N_NODES];
__device__ int   g_rowptr[N_NODES];
__device__ int   g_pos[N_EDGES];           // within-node slot (from hist)
__device__ int   g_csr[N_EDGES];
__device__ int   g_bsum[N_SCANB];

// ---------------------------------------------------------------------------
__device__ __forceinline__ float tf32r(float f) {
    uint32_t r;
    asm("cvt.rna.tf32.f32 %0, %1;" : "=r"(r) : "f"(f));
    return __uint_as_float(r);
}
__device__ __forceinline__ float4 tf32r4(float4 v) {
    return make_float4(tf32r(v.x), tf32r(v.y), tf32r(v.z), tf32r(v.w));
}
__device__ __forceinline__ void mma_tf32(float* d, const uint32_t* a, const uint32_t* b) {
    asm volatile(
        "mma.sync.aligned.m16n8k8.row.col.f32.tf32.tf32.f32 "
        "{%0,%1,%2,%3}, {%4,%5,%6,%7}, {%8,%9}, {%0,%1,%2,%3};"
        : "+f"(d[0]), "+f"(d[1]), "+f"(d[2]), "+f"(d[3])
        : "r"(a[0]), "r"(a[1]), "r"(a[2]), "r"(a[3]), "r"(b[0]), "r"(b[1]));
}
__device__ __forceinline__ uint32_t smem_u32(const void* p) {
    uint32_t a;
    asm("{ .reg .u64 t; cvta.to.shared.u64 t, %1; cvt.u32.u64 %0, t; }" : "=r"(a) : "l"(p));
    return a;
}
__device__ __forceinline__ void cpasync16(uint32_t dst, const void* src, int pred16) {
    asm volatile("cp.async.cg.shared.global [%0], [%1], 16, %2;"
                 :: "r"(dst), "l"(src), "r"(pred16) : "memory");
}
#define CP_COMMIT() asm volatile("cp.async.commit_group;" ::: "memory")
#define CP_WAIT0()  asm volatile("cp.async.wait_group 0;" ::: "memory")

// --------------------------- CSR build ------------------------------------
__global__ void hist_kernel(const int* __restrict__ ei) {
    int e4 = blockIdx.x * blockDim.x + threadIdx.x;
    if (e4 >= N_EDGES / 4) return;
    int4 d = ((const int4*)(ei + N_EDGES))[e4];
    int p0 = atomicAdd(&g_cnt[d.x], 1);
    int p1 = atomicAdd(&g_cnt[d.y], 1);
    int p2 = atomicAdd(&g_cnt[d.z], 1);
    int p3 = atomicAdd(&g_cnt[d.w], 1);
    ((int4*)g_pos)[e4] = make_int4(p0, p1, p2, p3);
}

__global__ void scan1_kernel() {
    __shared__ int ws[8];
    int b = blockIdx.x, t = threadIdx.x;
    int base = b * SCAN_B + t * 4;
    int c0 = (base + 0 < N_NODES) ? g_cnt[base + 0] : 0;
    int c1 = (base + 1 < N_NODES) ? g_cnt[base + 1] : 0;
    int c2 = (base + 2 < N_NODES) ? g_cnt[base + 2] : 0;
    int c3 = (base + 3 < N_NODES) ? g_cnt[base + 3] : 0;
    int s = c0 + c1 + c2 + c3;
    int lane = t & 31, w = t >> 5;
    int v = s;
    #pragma unroll
    for (int d = 1; d < 32; d <<= 1) {
        int u = __shfl_up_sync(~0u, v, d);
        if (lane >= d) v += u;
    }
    if (lane == 31) ws[w] = v;
    __syncthreads();
    if (t < 8) {
        int u = ws[t];
        #pragma unroll
        for (int d = 1; d < 8; d <<= 1) {
            int uu = __shfl_up_sync(0xffu, u, d);
            if (t >= d) u += uu;
        }
        ws[t] = u;
    }
    __syncthreads();
    int prefix = v - s + ((w > 0) ? ws[w - 1] : 0);
    int r0 = prefix, r1 = r0 + c0, r2 = r1 + c1, r3 = r2 + c2;
    if (base + 0 < N_NODES) g_rowptr[base + 0] = r0;
    if (base + 1 < N_NODES) g_rowptr[base + 1] = r1;
    if (base + 2 < N_NODES) g_rowptr[base + 2] = r2;
    if (base + 3 < N_NODES) g_rowptr[base + 3] = r3;
    if (t == 255) g_bsum[b] = ws[7];
}

__global__ void scan3_kernel() {
    __shared__ int red[256];
    __shared__ int off;
    int t = threadIdx.x;
    int sb = (blockIdx.x * 256) / SCAN_B;
    int partial = 0;
    for (int i = t; i < sb; i += 256) partial += g_bsum[i];
    red[t] = partial;
    __syncthreads();
    #pragma unroll
    for (int d = 128; d > 0; d >>= 1) {
        if (t < d) red[t] += red[t + d];
        __syncthreads();
    }
    if (t == 0) off = red[0];
    __syncthreads();
    int i = blockIdx.x * 256 + t;
    if (i >= N_NODES) return;
    g_rowptr[i] += off;
    g_invdeg[i] = 1.0f / fmaxf((float)g_cnt[i], 1.0f);
}

// fill: no atomics — slot comes from hist's g_pos; independent stores
__global__ void fill_kernel(const int* __restrict__ ei) {
    int e4 = blockIdx.x * blockDim.x + threadIdx.x;
    if (e4 >= N_EDGES / 4) return;
    int4 s = ((const int4*)ei)[e4];
    int4 d = ((const int4*)(ei + N_EDGES))[e4];
    int4 p = ((const int4*)g_pos)[e4];
    g_csr[g_rowptr[d.x] + p.x] = s.x;
    g_csr[g_rowptr[d.y] + p.y] = s.y;
    g_csr[g_rowptr[d.z] + p.z] = s.z;
    g_csr[g_rowptr[d.w] + p.w] = s.w;
}

// ------------------ Gather 1 (x -> agg, mean, tf32-rounded) -----------------
__global__ void gather_kernel(const float* __restrict__ vals,
                              float* __restrict__ aggm) {
    int gw = (blockIdx.x * blockDim.x + threadIdx.x) >> 5;
    if (gw >= N_NODES) return;
    int lane = threadIdx.x & 31;
    int start = g_rowptr[gw];
    int deg = g_cnt[gw];
    const float2* v2 = (const float2*)vals;
    float2 a0 = make_float2(0.f, 0.f), a1 = make_float2(0.f, 0.f);
    float2 a2 = make_float2(0.f, 0.f), a3 = make_float2(0.f, 0.f);
    int i = 0;
    for (; i + 4 <= deg; i += 4) {
        int s0 = g_csr[start + i];
        int s1 = g_csr[start + i + 1];
        int s2 = g_csr[start + i + 2];
        int s3 = g_csr[start + i + 3];
        float2 u0 = v2[(size_t)s0 * 32 + lane];
        float2 u1 = v2[(size_t)s1 * 32 + lane];
        float2 u2 = v2[(size_t)s2 * 32 + lane];
        float2 u3 = v2[(size_t)s3 * 32 + lane];
        a0.x += u0.x; a0.y += u0.y;
        a1.x += u1.x; a1.y += u1.y;
        a2.x += u2.x; a2.y += u2.y;
        a3.x += u3.x; a3.y += u3.y;
    }
    for (; i < deg; i++) {
        float2 u0 = v2[(size_t)g_csr[start + i] * 32 + lane];
        a0.x += u0.x; a0.y += u0.y;
    }
    float inv = g_invdeg[gw];
    ((float2*)aggm)[(size_t)gw * 32 + lane] =
        make_float2(tf32r(((a0.x + a1.x) + (a2.x + a3.x)) * inv),
                    tf32r(((a0.y + a1.y) + (a2.y + a3.y)) * inv));
}

// ------------------- Gather 2 fused with final epilogue ---------------------
__global__ void gather2_final_kernel(const float* __restrict__ hl,
                                     const float* __restrict__ b2l,
                                     float* __restrict__ out) {
    int gw = (blockIdx.x * blockDim.x + threadIdx.x) >> 5;
    if (gw >= N_NODES) return;
    int lane = threadIdx.x & 31;
    int start = g_rowptr[gw];
    int deg = g_cnt[gw];
    const float2* v2 = (const float2*)hl;
    float2 a0 = make_float2(0.f, 0.f), a1 = make_float2(0.f, 0.f);
    float2 a2 = make_float2(0.f, 0.f), a3 = make_float2(0.f, 0.f);
    int i = 0;
    for (; i + 4 <= deg; i += 4) {
        int s0 = g_csr[start + i];
        int s1 = g_csr[start + i + 1];
        int s2 = g_csr[start + i + 2];
        int s3 = g_csr[start + i + 3];
        float2 u0 = v2[(size_t)s0 * 32 + lane];
        float2 u1 = v2[(size_t)s1 * 32 + lane];
        float2 u2 = v2[(size_t)s2 * 32 + lane];
        float2 u3 = v2[(size_t)s3 * 32 + lane];
        a0.x += u0.x; a0.y += u0.y;
        a1.x += u1.x; a1.y += u1.y;
        a2.x += u2.x; a2.y += u2.y;
        a3.x += u3.x; a3.y += u3.y;
    }
    for (; i < deg; i++) {
        float2 u0 = v2[(size_t)g_csr[start + i] * 32 + lane];
        a0.x += u0.x; a0.y += u0.y;
    }
    float inv = g_invdeg[gw];
    float2 b = ((const float2*)b2l)[lane];
    float2* op = (float2*)out + (size_t)gw * 32 + lane;
    float2 y = *op;
    y.x += ((a0.x + a1.x) + (a2.x + a3.x)) * inv + b.x;
    y.y += ((a0.y + a1.y) + (a2.y + a3.y)) * inv + b.y;
    *op = y;
}

// --------------------------- tf32 mma.sync GEMM core ------------------------
__device__ __forceinline__ void gemm_core64(const float* sA, const float* sB,
                                            float acc[2][4][4],
                                            int g, int c, int wm, int wn) {
    #pragma unroll
    for (int ks = 0; ks < 16; ks++) {
        int K = ks * 8;
        uint32_t af[2][4];
        #pragma unroll
        for (int mt = 0; mt < 2; mt++) {
            const float* base = sA + (wm * 32 + mt * 16 + g) * PA + K + c;
            af[mt][0] = __float_as_uint(base[0]);
            af[mt][1] = __float_as_uint(base[8 * PA]);
            af[mt][2] = __float_as_uint(base[4]);
            af[mt][3] = __float_as_uint(base[8 * PA + 4]);
        }
        uint32_t bf[4][2];
        #pragma unroll
        for (int nt = 0; nt < 4; nt++) {
            const float* base = sB + (wn * 32 + nt * 8 + g) * PA + K + c;
            bf[nt][0] = __float_as_uint(base[0]);
            bf[nt][1] = __float_as_uint(base[4]);
        }
        #pragma unroll
        for (int mt = 0; mt < 2; mt++)
            #pragma unroll
            for (int nt = 0; nt < 4; nt++)
                mma_tf32(acc[mt][nt], af[mt], bf[nt]);
    }
}

// ----------- Layer 1 GEMM (persistent, B resident, prefetched A) ------------
__global__ void __launch_bounds__(256, 2)
layer1_mma_kernel(const float* __restrict__ x,
                  const float* __restrict__ W1l,
                  const float* __restrict__ b1l,
                  const float* __restrict__ W1r) {
    extern __shared__ float sm[];
    float* sA = sm;                        // 64 * PA
    float* sB = sm + 64 * PA;              // 128 * PA
    float* sbias = sm + 64 * PA + 128 * PA;
    uint32_t sA_u = smem_u32(sA);

    int t = threadIdx.x;
    int wid = t >> 5, lane = t & 31;
    int g = lane >> 2, c = lane & 3, wm = wid & 1, wn = wid >> 1;

    for (int i = t; i < 4096; i += 256) {
        int ch = i >> 5, f4 = i & 31;
        float4 w = (f4 < 16) ? ((const float4*)W1l)[ch * 16 + f4]
                             : ((const float4*)W1r)[ch * 16 + (f4 - 16)];
        *(float4*)&sB[ch * PA + f4 * 4] = tf32r4(w);
    }
    if (t < 128) sbias[t] = b1l[t];

    auto issueA = [&](int tile) {
        int n0 = tile * 64;
        #pragma unroll
        for (int s = 0; s < 4; s++) {
            int i = t + s * 256;
            int j = i >> 4, f4 = i & 15;
            int n = n0 + j;
            cpasync16(sA_u + (j * PA + f4 * 4) * 4,
                      g_agg + ((size_t)n * FEAT + f4 * 4),
                      (n < N_NODES) ? 16 : 0);
        }
        CP_COMMIT();
        #pragma unroll
        for (int s = 0; s < 4; s++) {
            int i = t + s * 256;
            int j = i >> 4, f4 = i & 15;
            int n = n0 + j;
            float4 v = make_float4(0.f, 0.f, 0.f, 0.f);
            if (n < N_NODES) v = ((const float4*)x)[(size_t)n * 16 + f4];
            *(float4*)&sA[j * PA + 64 + f4 * 4] = tf32r4(v);
        }
    };

    int tile = blockIdx.x;
    if (tile < NT64) issueA(tile);
    __syncthreads();

    for (; tile < NT64; tile += PGRID) {
        CP_WAIT0();
        __syncthreads();

        float acc[2][4][4];
        #pragma unroll
        for (int mt = 0; mt < 2; mt++)
            #pragma unroll
            for (int nt = 0; nt < 4; nt++)
                #pragma unroll
                for (int k = 0; k < 4; k++) acc[mt][nt][k] = 0.0f;

        gemm_core64(sA, sB, acc, g, c, wm, wn);
        __syncthreads();

        int next = tile + PGRID;
        if (next < NT64) issueA(next);

        int n0 = tile * 64;
        #pragma unroll
        for (int mt = 0; mt < 2; mt++) {
            int r0 = n0 + wm * 32 + mt * 16 + g;
            #pragma unroll
            for (int nt = 0; nt < 4; nt++) {
                int col = wn * 32 + nt * 8 + c * 2;
                float bx = sbias[col], by = sbias[col + 1];
                if (r0 < N_NODES)
                    *(float2*)&g_h[(size_t)r0 * HID + col] =
                        make_float2(tf32r(fmaxf(acc[mt][nt][0] + bx, 0.f)),
                                    tf32r(fmaxf(acc[mt][nt][1] + by, 0.f)));
                if (r0 + 8 < N_NODES)
                    *(float2*)&g_h[(size_t)(r0 + 8) * HID + col] =
                        make_float2(tf32r(fmaxf(acc[mt][nt][2] + bx, 0.f)),
                                    tf32r(fmaxf(acc[mt][nt][3] + by, 0.f)));
            }
        }
    }
}

// ------------- Layer 2 GEMM (persistent, B resident, cp.async A) ------------
__global__ void __launch_bounds__(256, 2)
gemm2_mma_kernel(const float* __restrict__ W2l,
                 const float* __restrict__ W2r,
                 float* __restrict__ out) {
    extern __shared__ float sm[];
    float* sA = sm;
    float* sB = sm + 64 * PA;
    uint32_t sA_u = smem_u32(sA);

    int t = threadIdx.x;
    int wid = t >> 5, lane = t & 31;
    int g = lane >> 2, c = lane & 3, wm = wid & 1, wn = wid >> 1;

    for (int i = t; i < 4096; i += 256) {
        int ch = i >> 5, f4 = i & 31;
        float4 w = (ch < 64) ? ((const float4*)W2l)[ch * 32 + f4]
                             : ((const float4*)W2r)[(ch - 64) * 32 + f4];
        *(float4*)&sB[ch * PA + f4 * 4] = tf32r4(w);
    }

    auto issueA = [&](int tile) {
        int n0 = tile * 64;
        #pragma unroll
        for (int s = 0; s < 8; s++) {
            int i = t + s * 256;
            int j = i >> 5, f4 = i & 31;
            int n = n0 + j;
            cpasync16(sA_u + (j * PA + f4 * 4) * 4,
                      (const char*)g_h + ((size_t)n * HID + f4 * 4) * 4,
                      (n < N_NODES) ? 16 : 0);
        }
        CP_COMMIT();
    };

    int tile = blockIdx.x;
    if (tile < NT64) issueA(tile);
    __syncthreads();

    for (; tile < NT64; tile += PGRID) {
        CP_WAIT0();
        __syncthreads();

        float acc[2][4][4];
        #pragma unroll
        for (int mt = 0; mt < 2; mt++)
            #pragma unroll
            for (int nt = 0; nt < 4; nt++)
                #pragma unroll
                for (int k = 0; k < 4; k++) acc[mt][nt][k] = 0.0f;

        gemm_core64(sA, sB, acc, g, c, wm, wn);
        __syncthreads();

        int next = tile + PGRID;
        if (next < NT64) issueA(next);

        int n0 = tile * 64;
        float* dst = (wn < 2) ? g_hl : out;
        int cbase = (wn < 2) ? 0 : 64;
        #pragma unroll
        for (int mt = 0; mt < 2; mt++) {
            int r0 = n0 + wm * 32 + mt * 16 + g;
            #pragma unroll
            for (int nt = 0; nt < 4; nt++) {
                int col = wn * 32 + nt * 8 + c * 2 - cbase;
                if (r0 < N_NODES)
                    *(float2*)&dst[(size_t)r0 * FEAT + col] = make_float2(acc[mt][nt][0], acc[mt][nt][1]);
                if (r0 + 8 < N_NODES)
                    *(float2*)&dst[(size_t)(r0 + 8) * FEAT + col] = make_float2(acc[mt][nt][2], acc[mt][nt][3]);
            }
        }
    }
}

// ---------------------------------------------------------------------------
extern "C" void kernel_launch(void* const* d_in, const int* in_sizes, int n_in,
                              void* d_out, int out_size) {
    const float* x   = (const float*)d_in[0];
    const int*   ei  = (const int*)d_in[1];
    const float* W1l = (const float*)d_in[2];
    const float* b1l = (const float*)d_in[3];
    const float* W1r = (const float*)d_in[4];
    const float* W2l = (const float*)d_in[5];
    const float* b2l = (const float*)d_in[6];
    const float* W2r = (const float*)d_in[7];
    float* out = (float*)d_out;

    float *agg, *hl;
    int *cnt;
    cudaGetSymbolAddress((void**)&agg, g_agg);
    cudaGetSymbolAddress((void**)&hl,  g_hl);
    cudaGetSymbolAddress((void**)&cnt, g_cnt);

    const int SMEM1 = (64 * PA + 128 * PA + 128) * 4;   // 101,888 B
    const int SMEM2 = (64 * PA + 128 * PA) * 4;         // 101,376 B
    cudaFuncSetAttribute(layer1_mma_kernel, cudaFuncAttributeMaxDynamicSharedMemorySize, SMEM1);
    cudaFuncSetAttribute(gemm2_mma_kernel,  cudaFuncAttributeMaxDynamicSharedMemorySize, SMEM2);

    // CSR build (atomic-free fill via hist slot capture)
    cudaMemsetAsync(cnt, 0, N_NODES * sizeof(int));
    hist_kernel<<<(N_EDGES / 4 + 255) / 256, 256>>>(ei);
    scan1_kernel<<<N_SCANB, 256>>>();
    scan3_kernel<<<(N_NODES + 255) / 256, 256>>>();
    fill_kernel<<<(N_EDGES / 4 + 255) / 256, 256>>>(ei);

    // Layer 1
    gather_kernel<<<(N_NODES * 32 + 255) / 256, 256>>>(x, agg);
    layer1_mma_kernel<<<PGRID, 256, SMEM1>>>(x, W1l, b1l, W1r);

    // Layer 2
    gemm2_mma_kernel<<<PGRID, 256, SMEM2>>>(W2l, W2r, out);
    gather2_final_kernel<<<(N_NODES * 32 + 255) / 256, 256>>>(hl, b2l, out);
}